// round 3
// baseline (speedup 1.0000x reference)
#include <cuda_runtime.h>

// HexEye: mean over 9x9 reflect-padded patches at 721 receptor centers,
// for 32 batches x 3 channels of a 600x800 fp32 image.
//
// d_in[0]: stim        float32 [32, 3, 600, 800]
// d_in[1]: receptor_x  int32   [721]
// d_in[2]: receptor_y  int32   [721]
// d_out  : float32 [32, 3, 721]
//
// One warp per (receptor, group-of-8 bc planes). Gather indices are identical
// across all 96 bc planes: each lane computes its reflect index once and
// issues 8 independent plane loads -> high MLP, tiny index-ALU share.

#define HEX_H     600
#define HEX_W     800
#define HEX_K     9
#define HEX_PAD   4
#define HEX_NOMM  721
#define HEX_BC    96
#define HEX_G     8                         // bc planes per warp
#define HEX_NGRP  (HEX_BC / HEX_G)          // 12
#define HEX_NWARP (HEX_NGRP * HEX_NOMM)     // 8652
#define PLANE     (HEX_H * HEX_W)

__global__ __launch_bounds__(256)
void hexeye_kernel(const float* __restrict__ stim,
                   const int*   __restrict__ receptor_x,
                   const int*   __restrict__ receptor_y,
                   float*       __restrict__ out)
{
    const int gwarp = (blockIdx.x * blockDim.x + threadIdx.x) >> 5;
    const int lane  = threadIdx.x & 31;
    if (gwarp >= HEX_NWARP) return;

    const int o   = gwarp % HEX_NOMM;   // receptor id
    const int grp = gwarp / HEX_NOMM;   // plane group (0..11)

    int cx = __ldg(&receptor_x[o]);
    int cy = __ldg(&receptor_y[o]);
    cx = min(max(cx, HEX_PAD), HEX_W + HEX_PAD - 1);
    cy = min(max(cy, HEX_PAD), HEX_H + HEX_PAD - 1);

    const float* __restrict__ img0 = stim + (size_t)(grp * HEX_G) * PLANE;

    float s[HEX_G];
    #pragma unroll
    for (int g = 0; g < HEX_G; g++) s[g] = 0.0f;

    #pragma unroll
    for (int i = 0; i < 3; i++) {
        const int idx = lane + 32 * i;      // 0..95, valid < 81
        if (idx < HEX_K * HEX_K) {
            const int dy = idx / HEX_K;
            const int dx = idx - dy * HEX_K;
            int m = cy + dy - 2 * HEX_PAD;  // [-4, 603]
            int n = cx + dx - 2 * HEX_PAD;  // [-4, 803]
            // jnp 'reflect' (no edge duplication)
            m = (m < 0) ? -m : ((m >= HEX_H) ? (2 * HEX_H - 2 - m) : m);
            n = (n < 0) ? -n : ((n >= HEX_W) ? (2 * HEX_W - 2 - n) : n);
            const int off = m * HEX_W + n;

            // issue all 8 loads before consuming any (independent temps)
            float v[HEX_G];
            #pragma unroll
            for (int g = 0; g < HEX_G; g++)
                v[g] = __ldg(&img0[off + g * PLANE]);
            #pragma unroll
            for (int g = 0; g < HEX_G; g++)
                s[g] += v[g];
        }
    }

    // warp tree reductions (8 accumulators, pipelined shuffles)
    #pragma unroll
    for (int off = 16; off > 0; off >>= 1) {
        #pragma unroll
        for (int g = 0; g < HEX_G; g++)
            s[g] += __shfl_xor_sync(0xffffffffu, s[g], off);
    }

    if (lane == 0) {
        const float inv = 1.0f / 81.0f;
        float* op = out + (size_t)(grp * HEX_G) * HEX_NOMM + o;
        #pragma unroll
        for (int g = 0; g < HEX_G; g++)
            op[g * HEX_NOMM] = s[g] * inv;
    }
}

extern "C" void kernel_launch(void* const* d_in, const int* in_sizes, int n_in,
                              void* d_out, int out_size)
{
    const float* stim = (const float*)d_in[0];
    const int*   rx   = (const int*)d_in[1];
    const int*   ry   = (const int*)d_in[2];
    float*       out  = (float*)d_out;

    const int warps_per_block = 256 / 32;  // 8
    const int nblocks = (HEX_NWARP + warps_per_block - 1) / warps_per_block; // 1082

    hexeye_kernel<<<nblocks, 256>>>(stim, rx, ry, out);
}